// round 8
// baseline (speedup 1.0000x reference)
#include <cuda_runtime.h>
#include <cuda_bf16.h>
#include <cstdint>

#define NROWS 16384
#define DD    128
#define BM    128
#define BN    128
#define KSPLIT 2
#define TILES_PER (NROWS / BN / KSPLIT)   // 64
#define NTHREADS 128

// device globals (allocation-free rule)
__device__ __nv_bfloat16 g_nx[NROWS * DD];          // normalized rows (K == V base)
__device__ float         g_norm[NROWS];             // row norms
__device__ float         g_opart[KSPLIT][NROWS][DD];  // split-K O partials (16 MB)
__device__ float         g_dpart[KSPLIT][NROWS];      // split-K den partials

// ---------------------------------------------------------------------------
__device__ __forceinline__ uint32_t smem_u32(const void* p) {
    uint32_t a;
    asm("{ .reg .u64 t; cvta.to.shared.u64 t, %1; cvt.u32.u64 %0, t; }"
        : "=r"(a) : "l"(p));
    return a;
}
__device__ __forceinline__ void cpa16(uint32_t dst, const void* src) {
    asm volatile("cp.async.cg.shared.global [%0], [%1], 16;"
                 :: "r"(dst), "l"(src) : "memory");
}
#define CP_COMMIT() asm volatile("cp.async.commit_group;" ::: "memory")
#define CP_WAIT1()  asm volatile("cp.async.wait_group 1;" ::: "memory")
#define CP_WAIT0()  asm volatile("cp.async.wait_group 0;" ::: "memory")

__device__ __forceinline__ void ldsm4(uint32_t* r, uint32_t addr) {
    asm volatile("ldmatrix.sync.aligned.m8n8.x4.shared.b16 {%0,%1,%2,%3}, [%4];"
        : "=r"(r[0]), "=r"(r[1]), "=r"(r[2]), "=r"(r[3]) : "r"(addr));
}
__device__ __forceinline__ void ldsm4t(uint32_t* r, uint32_t addr) {
    asm volatile("ldmatrix.sync.aligned.m8n8.x4.trans.shared.b16 {%0,%1,%2,%3}, [%4];"
        : "=r"(r[0]), "=r"(r[1]), "=r"(r[2]), "=r"(r[3]) : "r"(addr));
}
__device__ __forceinline__ void mma16816(float* c, const uint32_t* a,
                                         uint32_t b0, uint32_t b1) {
    asm volatile("mma.sync.aligned.m16n8k16.row.col.f32.bf16.bf16.f32 "
        "{%0,%1,%2,%3}, {%4,%5,%6,%7}, {%8,%9}, {%0,%1,%2,%3};"
        : "+f"(c[0]), "+f"(c[1]), "+f"(c[2]), "+f"(c[3])
        : "r"(a[0]), "r"(a[1]), "r"(a[2]), "r"(a[3]), "r"(b0), "r"(b1));
}
__device__ __forceinline__ uint32_t packbf(float lo, float hi) {
    uint32_t d;
    asm("cvt.rn.bf16x2.f32 %0, %1, %2;" : "=r"(d) : "f"(hi), "f"(lo));
    return d;
}
// Degree-7 Taylor exp, s in [-1,1]: rel err < 3e-5, pure FFMA
__device__ __forceinline__ float expp(float s) {
    float p = 1.9841270e-4f;
    p = fmaf(p, s, 1.3888889e-3f);
    p = fmaf(p, s, 8.3333333e-3f);
    p = fmaf(p, s, 4.1666667e-2f);
    p = fmaf(p, s, 1.6666667e-1f);
    p = fmaf(p, s, 0.5f);
    p = fmaf(p, s, 1.0f);
    p = fmaf(p, s, 1.0f);
    return p;
}
// Tile smem layout: row r (0..127) * 256B, 16B chunk c swizzled by row
__device__ __forceinline__ uint32_t toff(int r, int c) {
    return (uint32_t)(r * 256 + ((c ^ (r & 7)) << 4));
}

#define STG_NX(s) ((s) * 32768)
#define STG_KN(s) (65536 + (s) * 512)
#define SMEM_BYTES (65536 + 1024)

// ---------------------------------------------------------------------------
__global__ void prep_kernel(const float* __restrict__ x) {
    int row  = blockIdx.x * 8 + (threadIdx.x >> 5);
    int lane = threadIdx.x & 31;
    float4 v = *(const float4*)(x + (size_t)row * DD + lane * 4);
    float ss = v.x * v.x + v.y * v.y + v.z * v.z + v.w * v.w;
    #pragma unroll
    for (int o = 16; o; o >>= 1) ss += __shfl_xor_sync(0xffffffffu, ss, o);
    float nrm = sqrtf(ss);
    float inv = 1.0f / fmaxf(nrm, 1e-12f);
    size_t base = (size_t)row * DD + lane * 4;
    *(__nv_bfloat162*)(g_nx + base)     = __floats2bfloat162_rn(v.x * inv, v.y * inv);
    *(__nv_bfloat162*)(g_nx + base + 2) = __floats2bfloat162_rn(v.z * inv, v.w * inv);
    if (lane == 0) g_norm[row] = nrm;
}

// ---------------------------------------------------------------------------
__device__ __forceinline__ void prefetch_tile(int tt, int tend, uint32_t sb, int tid) {
    if (tt < tend) {
        uint32_t nb = sb + STG_NX(tt & 1);
        int j0 = tt * BN;
        #pragma unroll
        for (int i = 0; i < 16; i++) {
            int idx = tid + i * NTHREADS;
            int r = idx >> 4, c = idx & 15;
            cpa16(nb + toff(r, c), g_nx + (size_t)(j0 + r) * DD + c * 8);
        }
        if (tid < 32)
            cpa16(sb + STG_KN(tt & 1) + tid * 16, g_norm + j0 + tid * 4);
    }
    CP_COMMIT();
}

// ---------------------------------------------------------------------------
// Split-K attention partial: BM=128 queries, 4 warps x 32 rows, half the keys.
// Writes O partial + den partial to global scratch. Fused per-group S->exp->O.
// ---------------------------------------------------------------------------
__global__ __launch_bounds__(NTHREADS, 2)
void attn_kernel() {
    extern __shared__ char smem[];
    uint32_t sb = smem_u32(smem);
    const int tid  = threadIdx.x;
    const int wid  = tid >> 5;
    const int lane = tid & 31;
    const int qt   = blockIdx.x >> 1;
    const int half = blockIdx.x & 1;
    const int i0   = qt * BM;
    const int t0   = half * TILES_PER;
    const int tend = t0 + TILES_PER;

    // ---- stage Q tile (128 rows) into stage0, load Q fragments (2 rowblocks) ----
    {
        uint32_t qb = sb + STG_NX(0);
        #pragma unroll
        for (int i = 0; i < 16; i++) {
            int idx = tid + i * NTHREADS;
            int r = idx >> 4, c = idx & 15;
            cpa16(qb + toff(r, c), g_nx + (size_t)(i0 + r) * DD + c * 8);
        }
        CP_COMMIT(); CP_WAIT0();
    }
    __syncthreads();

    uint32_t q[2][8][4];
    #pragma unroll
    for (int rb = 0; rb < 2; rb++) {
        int rbase = wid * 32 + rb * 16 + (lane & 7) + ((lane >> 3) & 1) * 8;
        #pragma unroll
        for (int kk = 0; kk < 8; kk++)
            ldsm4(q[rb][kk], sb + STG_NX(0) + toff(rbase, 2 * kk + (lane >> 4)));
    }
    __syncthreads();

    prefetch_tile(t0, tend, sb, tid);
    prefetch_tile(t0 + 1, tend, sb, tid);

    float o[2][16][4];
    #pragma unroll
    for (int rb = 0; rb < 2; rb++)
        #pragma unroll
        for (int j = 0; j < 16; j++)
            #pragma unroll
            for (int c = 0; c < 4; c++) o[rb][j][c] = 0.0f;
    float den[2][2] = {{0, 0}, {0, 0}};

    const int klr = lane & 7;
    const int kg1 = (lane >> 3) & 1;
    const int kg2 = lane >> 4;
    const int jq  = 2 * (lane & 3);

    for (int t = 0; t < TILES_PER; t++) {
        const int tt = t0 + t;
        uint32_t nb  = sb + STG_NX(tt & 1);
        uint32_t knb = sb + STG_KN(tt & 1);
        CP_WAIT1();
        __syncthreads();

        #pragma unroll
        for (int g = 0; g < 8; g++) {
            // ---- S = Q.K^T, both rowblocks share each B fragment ----
            float s[2][2][4] = {{{0,0,0,0},{0,0,0,0}},{{0,0,0,0},{0,0,0,0}}};
            int krow = g * 16 + kg2 * 8 + klr;
            #pragma unroll
            for (int kk = 0; kk < 8; kk++) {
                uint32_t b[4];
                ldsm4(b, nb + toff(krow, 2 * kk + kg1));
                mma16816(s[0][0], q[0][kk], b[0], b[1]);
                mma16816(s[0][1], q[0][kk], b[2], b[3]);
                mma16816(s[1][0], q[1][kk], b[0], b[1]);
                mma16816(s[1][1], q[1][kk], b[2], b[3]);
            }
            // ---- exp + fold key norm + pack (A-frag layout) ----
            float2 kn01, kn89;
            asm("ld.shared.v2.f32 {%0,%1}, [%2];" : "=f"(kn01.x), "=f"(kn01.y)
                : "r"(knb + (g * 16 + jq) * 4));
            asm("ld.shared.v2.f32 {%0,%1}, [%2];" : "=f"(kn89.x), "=f"(kn89.y)
                : "r"(knb + (g * 16 + 8 + jq) * 4));
            uint32_t pk[2][4];
            #pragma unroll
            for (int rb = 0; rb < 2; rb++) {
                float e00 = expp(s[rb][0][0]), e01 = expp(s[rb][0][1]);
                float e02 = expp(s[rb][0][2]), e03 = expp(s[rb][0][3]);
                float e10 = expp(s[rb][1][0]), e11 = expp(s[rb][1][1]);
                float e12 = expp(s[rb][1][2]), e13 = expp(s[rb][1][3]);
                den[rb][0] += e00 + e01 + e10 + e11;
                den[rb][1] += e02 + e03 + e12 + e13;
                pk[rb][0] = packbf(e00 * kn01.x, e01 * kn01.y);
                pk[rb][1] = packbf(e02 * kn01.x, e03 * kn01.y);
                pk[rb][2] = packbf(e10 * kn89.x, e11 * kn89.y);
                pk[rb][3] = packbf(e12 * kn89.x, e13 * kn89.y);
            }
            // ---- O += P[:,g] . NX[g,:], both rowblocks share each V fragment ----
            int vrow = g * 16 + kg1 * 8 + klr;
            #pragma unroll
            for (int dg = 0; dg < 8; dg++) {
                uint32_t v[4];
                ldsm4t(v, nb + toff(vrow, 2 * dg + kg2));
                mma16816(o[0][2 * dg],     pk[0], v[0], v[1]);
                mma16816(o[0][2 * dg + 1], pk[0], v[2], v[3]);
                mma16816(o[1][2 * dg],     pk[1], v[0], v[1]);
                mma16816(o[1][2 * dg + 1], pk[1], v[2], v[3]);
            }
        }

        __syncthreads();
        prefetch_tile(tt + 2, tend, sb, tid);
    }

    // ---- write partials: den (quad-reduced) + O frags ----
    #pragma unroll
    for (int rb = 0; rb < 2; rb++) {
        den[rb][0] += __shfl_xor_sync(0xffffffffu, den[rb][0], 1);
        den[rb][0] += __shfl_xor_sync(0xffffffffu, den[rb][0], 2);
        den[rb][1] += __shfl_xor_sync(0xffffffffu, den[rb][1], 1);
        den[rb][1] += __shfl_xor_sync(0xffffffffu, den[rb][1], 2);
        int ra = i0 + wid * 32 + rb * 16 + (lane >> 2);
        if ((lane & 3) == 0) {
            g_dpart[half][ra]     = den[rb][0];
            g_dpart[half][ra + 8] = den[rb][1];
        }
        #pragma unroll
        for (int j = 0; j < 16; j++) {
            int col = 8 * j + jq;
            *(float2*)&g_opart[half][ra][col]     = make_float2(o[rb][j][0], o[rb][j][1]);
            *(float2*)&g_opart[half][ra + 8][col] = make_float2(o[rb][j][2], o[rb][j][3]);
        }
    }
}

// ---------------------------------------------------------------------------
// Epilogue: combine split-K partials, y = 1.5x - 0.5*O/den, LayerNorm.
// One warp per row; 8 rows per 256-thread block.
// ---------------------------------------------------------------------------
__global__ __launch_bounds__(256)
void ln_kernel(const float* __restrict__ x,
               const float* __restrict__ gamma,
               const float* __restrict__ beta,
               float* __restrict__ out) {
    const int row  = blockIdx.x * 8 + (threadIdx.x >> 5);
    const int lane = threadIdx.x & 31;
    const int c    = lane * 4;

    float4 o0 = *(const float4*)&g_opart[0][row][c];
    float4 o1 = *(const float4*)&g_opart[1][row][c];
    const float den = g_dpart[0][row] + g_dpart[1][row];
    const float inv = 0.5f / den;   // folds SCALE=-0.5
    float4 xv = *(const float4*)(x + (size_t)row * DD + c);

    float y0 = fmaf(1.5f, xv.x, -(o0.x + o1.x) * inv);
    float y1 = fmaf(1.5f, xv.y, -(o0.y + o1.y) * inv);
    float y2 = fmaf(1.5f, xv.z, -(o0.z + o1.z) * inv);
    float y3 = fmaf(1.5f, xv.w, -(o0.w + o1.w) * inv);

    float s1 = y0 + y1 + y2 + y3;
    float s2 = fmaf(y0, y0, fmaf(y1, y1, fmaf(y2, y2, y3 * y3)));
    #pragma unroll
    for (int o = 16; o; o >>= 1) {
        s1 += __shfl_xor_sync(0xffffffffu, s1, o);
        s2 += __shfl_xor_sync(0xffffffffu, s2, o);
    }
    const float mu   = s1 * (1.0f / DD);
    const float var  = s2 * (1.0f / DD) - mu * mu;
    const float rstd = rsqrtf(var + 1e-5f);

    float4 gm = *(const float4*)(gamma + c);
    float4 bt = *(const float4*)(beta + c);
    float4 r;
    r.x = fmaf((y0 - mu) * rstd, gm.x, bt.x);
    r.y = fmaf((y1 - mu) * rstd, gm.y, bt.y);
    r.z = fmaf((y2 - mu) * rstd, gm.z, bt.z);
    r.w = fmaf((y3 - mu) * rstd, gm.w, bt.w);
    *(float4*)(out + (size_t)row * DD + c) = r;
}

// ---------------------------------------------------------------------------
extern "C" void kernel_launch(void* const* d_in, const int* in_sizes, int n_in,
                              void* d_out, int out_size) {
    const float* x     = (const float*)d_in[0];
    const float* gamma = (const float*)d_in[1];
    const float* beta  = (const float*)d_in[2];
    float* out = (float*)d_out;

    prep_kernel<<<NROWS / 8, 256>>>(x);

    cudaFuncSetAttribute(attn_kernel,
                         cudaFuncAttributeMaxDynamicSharedMemorySize, SMEM_BYTES);
    attn_kernel<<<(NROWS / BM) * KSPLIT, NTHREADS, SMEM_BYTES>>>();

    ln_kernel<<<NROWS / 8, 256>>>(x, gamma, beta, out);
}